// round 6
// baseline (speedup 1.0000x reference)
#include <cuda_runtime.h>
#include <math.h>

// ChamferReward — R6: single fused kernel (threadfence last-block reduction),
// CJP=16 chunks. Inner loop identical math to R5: packed fma.rn.f32x2 distance
// (bb - 2 a.b, two j per chain), dual scalar fminf chains, chunk fold with
// strict < (first chunk wins), winning chunk rescanned bit-identically with
// exact == (lo before hi) => jnp.argmin first-occurrence semantics.

#define N_PART  1024
#define NJP     512
#define THREADS 256
#define ITEMS   4
#define CJP     16              // jp per chunk (32 j)
#define NCHUNK  (NJP / CJP)     // 32
#define NCTA    1024

typedef unsigned long long ull;

__device__ float g_partials[NCTA];
__device__ unsigned int g_arrived = 0;

#define FMA2(d, a, b, c) \
    asm("fma.rn.f32x2 %0, %1, %2, %3;" : "=l"(d) : "l"(a), "l"(b), "l"(c))

__device__ __forceinline__ ull pack_dup(float x) {
    ull r;
    unsigned xi = __float_as_uint(x);
    asm("mov.b64 %0, {%1, %1};" : "=l"(r) : "r"(xi));
    return r;
}

__device__ __forceinline__ void unpack2(ull v, float& lo, float& hi) {
    unsigned a, b;
    asm("mov.b64 {%0, %1}, %2;" : "=r"(a), "=r"(b) : "l"(v));
    lo = __uint_as_float(a);
    hi = __uint_as_float(b);
}

__global__ void __launch_bounds__(THREADS, 2)
chamfer_pass_kernel(const float* __restrict__ achieved,
                    const float* __restrict__ desired,
                    const float* __restrict__ norm_mean,
                    const float* __restrict__ norm_std,
                    float* __restrict__ out)
{
    __shared__ ulonglong2 sb01[NJP];   // 8KB: {b0 pair, b1 pair}
    __shared__ ulonglong2 sb23[NJP];   // 8KB: {b2 pair, b3 pair}
    __shared__ ull        sbb[NJP];    // 4KB: |b|^2 pair
    __shared__ float2     sxy[N_PART]; // 8KB
    __shared__ float      warp_sums[THREADS / 32];
    __shared__ unsigned int s_rank;

    const int c    = blockIdx.x;
    const int pass = c & 1;
    const int bv   = c >> 1;

    const float* ownp;
    const float* strp;
    if (pass == 0) { ownp = desired;  strp = achieved; }
    else           { ownp = achieved; strp = desired;  }
    const size_t base = (size_t)bv * (size_t)N_PART * 10;
    ownp += base;
    strp += base;

    const float m0 = __ldg(norm_mean + 0), m1 = __ldg(norm_mean + 1);
    const float m5 = __ldg(norm_mean + 5), m6 = __ldg(norm_mean + 6);
    const float m7 = __ldg(norm_mean + 7), m8 = __ldg(norm_mean + 8);
    const float s0 = __ldg(norm_std  + 0), s1 = __ldg(norm_std  + 1);
    const float s5 = __ldg(norm_std  + 5), s6 = __ldg(norm_std  + 6);
    const float s7 = __ldg(norm_std  + 7), s8 = __ldg(norm_std  + 8);

    const int tid = threadIdx.x;

    // ---- Stage streamed side (normalize, precompute |vis|^2) ----
    {
        float* f01 = (float*)sb01;   // per jp: [b0_lo, b0_hi, b1_lo, b1_hi]
        float* f23 = (float*)sb23;   // per jp: [b2_lo, b2_hi, b3_lo, b3_hi]
        float* fbb = (float*)sbb;    // contiguous over j
        for (int i = tid; i < N_PART; i += THREADS) {
            const float* r = strp + i * 10;
            float x0 = fmaf(r[0], s0, m0);
            float x1 = fmaf(r[1], s1, m1);
            float v0 = fmaf(r[5], s5, m5);
            float v1 = fmaf(r[6], s6, m6);
            float v2 = fmaf(r[7], s7, m7);
            float v3 = fmaf(r[8], s8, m8);
            const int jp = i >> 1, h = i & 1;
            f01[jp * 4 + h]     = v0;
            f01[jp * 4 + 2 + h] = v1;
            f23[jp * 4 + h]     = v2;
            f23[jp * 4 + 2 + h] = v3;
            fbb[i] = v0 * v0 + v1 * v1 + v2 * v2 + v3 * v3;
            sxy[i] = make_float2(x0, x1);
        }
    }

    // ---- Owned items: a' = -2a, duplicated into both packed halves ----
    ull a0d[ITEMS], a1d[ITEMS], a2d[ITEMS], a3d[ITEMS];
    float aa[ITEMS], ox[ITEMS], oy[ITEMS];
#pragma unroll
    for (int k = 0; k < ITEMS; k++) {
        const int i = tid + k * THREADS;
        const float* r = ownp + i * 10;
        ox[k] = fmaf(r[0], s0, m0);
        oy[k] = fmaf(r[1], s1, m1);
        float a0 = fmaf(r[5], s5, m5);
        float a1 = fmaf(r[6], s6, m6);
        float a2 = fmaf(r[7], s7, m7);
        float a3 = fmaf(r[8], s8, m8);
        aa[k] = a0 * a0 + a1 * a1 + a2 * a2 + a3 * a3;
        a0d[k] = pack_dup(-2.0f * a0);
        a1d[k] = pack_dup(-2.0f * a1);
        a2d[k] = pack_dup(-2.0f * a2);
        a3d[k] = pack_dup(-2.0f * a3);
    }

    __syncthreads();

    // ---- Main loop: dual-chain value-only chunk minima ----
    float bestd[ITEMS];
    int   bestc[ITEMS];
#pragma unroll
    for (int k = 0; k < ITEMS; k++) { bestd[k] = 3.4e38f; bestc[k] = 0; }

    for (int ch = 0; ch < NCHUNK; ch++) {
        float clo[ITEMS], chi[ITEMS];
#pragma unroll
        for (int k = 0; k < ITEMS; k++) { clo[k] = 3.4e38f; chi[k] = 3.4e38f; }

#pragma unroll
        for (int u = 0; u < CJP; u++) {
            const int jp = ch * CJP + u;
            const ulonglong2 p01 = sb01[jp];
            const ulonglong2 p23 = sb23[jp];
            const ull        acc = sbb[jp];
#pragma unroll
            for (int k = 0; k < ITEMS; k++) {
                ull t;
                FMA2(t, a0d[k], p01.x, acc);
                FMA2(t, a1d[k], p01.y, t);
                FMA2(t, a2d[k], p23.x, t);
                FMA2(t, a3d[k], p23.y, t);
                float lo, hi;
                unpack2(t, lo, hi);       // register-naming only
                clo[k] = fminf(clo[k], lo);
                chi[k] = fminf(chi[k], hi);
            }
        }
#pragma unroll
        for (int k = 0; k < ITEMS; k++) {
            const float m = fminf(clo[k], chi[k]);
            if (m < bestd[k]) { bestd[k] = m; bestc[k] = ch; }  // strict <: first chunk wins
        }
    }

    // ---- Rescan winning chunk per item: recover first argmin index exactly ----
    float partial = 0.0f;
#pragma unroll
    for (int k = 0; k < ITEMS; k++) {
        const float bd = bestd[k];
        const int jp0 = bestc[k] * CJP;
        int jbest = jp0 * 2;
        bool found = false;
        for (int u = 0; u < CJP; u++) {
            const int jp = jp0 + u;
            const ulonglong2 p01 = sb01[jp];
            const ulonglong2 p23 = sb23[jp];
            const ull        acc = sbb[jp];
            ull t;
            FMA2(t, a0d[k], p01.x, acc);
            FMA2(t, a1d[k], p01.y, t);
            FMA2(t, a2d[k], p23.x, t);
            FMA2(t, a3d[k], p23.y, t);
            float lo, hi;
            unpack2(t, lo, hi);
            if (!found && lo == bd) { jbest = jp * 2;     found = true; }
            if (!found && hi == bd) { jbest = jp * 2 + 1; found = true; }
        }

        const float2 p = sxy[jbest];
        const float dx = ox[k] - p.x;
        const float dy = oy[k] - p.y;
        float xd = sqrtf(dx * dx + dy * dy);
        const float min_d = aa[k] + bd;     // true squared latent distance
        if (min_d > 6.0f) xd = 1.0f;        // LATENT_DIST_THRESHOLD
        partial += xd;
    }

    // ---- Block reduce (deterministic) ----
#pragma unroll
    for (int off = 16; off > 0; off >>= 1)
        partial += __shfl_down_sync(0xffffffffu, partial, off);
    if ((tid & 31) == 0) warp_sums[tid >> 5] = partial;
    __syncthreads();
    if (tid == 0) {
        float s = 0.0f;
#pragma unroll
        for (int w = 0; w < THREADS / 32; w++) s += warp_sums[w];
        g_partials[c] = s;
        __threadfence();
        // Arrival counter: last CTA performs the final reduction.
        s_rank = atomicAdd(&g_arrived, 1u);
    }
    __syncthreads();

    if (s_rank == NCTA - 1) {
        __threadfence();                    // acquire partials
        if (tid < 128) {
            float s = 0.0f;
#pragma unroll
            for (int t = 0; t < 8; t++) s += g_partials[tid * 8 + t];
            out[tid] = -s * (1.0f / (1024.0f * 8.0f));
        }
        __syncthreads();
        if (tid == 0) g_arrived = 0;        // reset for next graph replay
    }
}

extern "C" void kernel_launch(void* const* d_in, const int* in_sizes, int n_in,
                              void* d_out, int out_size)
{
    const float* achieved  = (const float*)d_in[0];
    const float* desired   = (const float*)d_in[1];
    const float* norm_mean = (const float*)d_in[2];
    const float* norm_std  = (const float*)d_in[3];
    float* out = (float*)d_out;

    chamfer_pass_kernel<<<NCTA, THREADS>>>(achieved, desired, norm_mean, norm_std, out);
}

// round 7
// speedup vs baseline: 1.2016x; 1.2016x over previous
#include <cuda_runtime.h>
#include <math.h>

// ChamferReward — R7: fused kernel (threadfence last-block reduction) with the
// proven CJP=8 chunk window (CJP=16 pegged regs at the 128 cap and spilled ->
// L1 65.9% / 293us in R6; CJP=8 ran spill-free in R5).
//
// Inner loop per (item, jp): 4 chained fma.rn.f32x2 (bb - 2 a.b, two j's) +
// 2 scalar fminf chains (lo/hi). Chunk fold strict < (first chunk wins);
// winning chunk rescanned with bit-identical FMA order + exact == (lo before
// hi) => jnp.argmin first-occurrence semantics preserved exactly.

#define N_PART  1024
#define NJP     512
#define THREADS 256
#define ITEMS   4
#define CJP     8               // jp per chunk (16 j) — no-spill window
#define NCHUNK  (NJP / CJP)     // 64
#define NCTA    1024

typedef unsigned long long ull;

__device__ float g_partials[NCTA];
__device__ unsigned int g_arrived = 0;

#define FMA2(d, a, b, c) \
    asm("fma.rn.f32x2 %0, %1, %2, %3;" : "=l"(d) : "l"(a), "l"(b), "l"(c))

__device__ __forceinline__ ull pack_dup(float x) {
    ull r;
    unsigned xi = __float_as_uint(x);
    asm("mov.b64 %0, {%1, %1};" : "=l"(r) : "r"(xi));
    return r;
}

__device__ __forceinline__ void unpack2(ull v, float& lo, float& hi) {
    unsigned a, b;
    asm("mov.b64 {%0, %1}, %2;" : "=r"(a), "=r"(b) : "l"(v));
    lo = __uint_as_float(a);
    hi = __uint_as_float(b);
}

__global__ void __launch_bounds__(THREADS, 2)
chamfer_pass_kernel(const float* __restrict__ achieved,
                    const float* __restrict__ desired,
                    const float* __restrict__ norm_mean,
                    const float* __restrict__ norm_std,
                    float* __restrict__ out)
{
    __shared__ ulonglong2 sb01[NJP];   // 8KB: {b0 pair, b1 pair}
    __shared__ ulonglong2 sb23[NJP];   // 8KB: {b2 pair, b3 pair}
    __shared__ ull        sbb[NJP];    // 4KB: |b|^2 pair
    __shared__ float2     sxy[N_PART]; // 8KB
    __shared__ float      warp_sums[THREADS / 32];
    __shared__ unsigned int s_rank;

    const int c    = blockIdx.x;
    const int pass = c & 1;
    const int bv   = c >> 1;

    const float* ownp;
    const float* strp;
    if (pass == 0) { ownp = desired;  strp = achieved; }
    else           { ownp = achieved; strp = desired;  }
    const size_t base = (size_t)bv * (size_t)N_PART * 10;
    ownp += base;
    strp += base;

    const float m0 = __ldg(norm_mean + 0), m1 = __ldg(norm_mean + 1);
    const float m5 = __ldg(norm_mean + 5), m6 = __ldg(norm_mean + 6);
    const float m7 = __ldg(norm_mean + 7), m8 = __ldg(norm_mean + 8);
    const float s0 = __ldg(norm_std  + 0), s1 = __ldg(norm_std  + 1);
    const float s5 = __ldg(norm_std  + 5), s6 = __ldg(norm_std  + 6);
    const float s7 = __ldg(norm_std  + 7), s8 = __ldg(norm_std  + 8);

    const int tid = threadIdx.x;

    // ---- Stage streamed side (normalize, precompute |vis|^2) ----
    {
        float* f01 = (float*)sb01;   // per jp: [b0_lo, b0_hi, b1_lo, b1_hi]
        float* f23 = (float*)sb23;   // per jp: [b2_lo, b2_hi, b3_lo, b3_hi]
        float* fbb = (float*)sbb;    // contiguous over j
        for (int i = tid; i < N_PART; i += THREADS) {
            const float* r = strp + i * 10;
            float x0 = fmaf(r[0], s0, m0);
            float x1 = fmaf(r[1], s1, m1);
            float v0 = fmaf(r[5], s5, m5);
            float v1 = fmaf(r[6], s6, m6);
            float v2 = fmaf(r[7], s7, m7);
            float v3 = fmaf(r[8], s8, m8);
            const int jp = i >> 1, h = i & 1;
            f01[jp * 4 + h]     = v0;
            f01[jp * 4 + 2 + h] = v1;
            f23[jp * 4 + h]     = v2;
            f23[jp * 4 + 2 + h] = v3;
            fbb[i] = v0 * v0 + v1 * v1 + v2 * v2 + v3 * v3;
            sxy[i] = make_float2(x0, x1);
        }
    }

    // ---- Owned items: a' = -2a, duplicated into both packed halves ----
    ull a0d[ITEMS], a1d[ITEMS], a2d[ITEMS], a3d[ITEMS];
    float aa[ITEMS], ox[ITEMS], oy[ITEMS];
#pragma unroll
    for (int k = 0; k < ITEMS; k++) {
        const int i = tid + k * THREADS;
        const float* r = ownp + i * 10;
        ox[k] = fmaf(r[0], s0, m0);
        oy[k] = fmaf(r[1], s1, m1);
        float a0 = fmaf(r[5], s5, m5);
        float a1 = fmaf(r[6], s6, m6);
        float a2 = fmaf(r[7], s7, m7);
        float a3 = fmaf(r[8], s8, m8);
        aa[k] = a0 * a0 + a1 * a1 + a2 * a2 + a3 * a3;
        a0d[k] = pack_dup(-2.0f * a0);
        a1d[k] = pack_dup(-2.0f * a1);
        a2d[k] = pack_dup(-2.0f * a2);
        a3d[k] = pack_dup(-2.0f * a3);
    }

    __syncthreads();

    // ---- Main loop: dual-chain value-only chunk minima ----
    float bestd[ITEMS];
    int   bestc[ITEMS];
#pragma unroll
    for (int k = 0; k < ITEMS; k++) { bestd[k] = 3.4e38f; bestc[k] = 0; }

    for (int ch = 0; ch < NCHUNK; ch++) {
        float clo[ITEMS], chi[ITEMS];
#pragma unroll
        for (int k = 0; k < ITEMS; k++) { clo[k] = 3.4e38f; chi[k] = 3.4e38f; }

#pragma unroll
        for (int u = 0; u < CJP; u++) {
            const int jp = ch * CJP + u;
            const ulonglong2 p01 = sb01[jp];
            const ulonglong2 p23 = sb23[jp];
            const ull        acc = sbb[jp];
#pragma unroll
            for (int k = 0; k < ITEMS; k++) {
                ull t;
                FMA2(t, a0d[k], p01.x, acc);
                FMA2(t, a1d[k], p01.y, t);
                FMA2(t, a2d[k], p23.x, t);
                FMA2(t, a3d[k], p23.y, t);
                float lo, hi;
                unpack2(t, lo, hi);       // register-naming only
                clo[k] = fminf(clo[k], lo);
                chi[k] = fminf(chi[k], hi);
            }
        }
#pragma unroll
        for (int k = 0; k < ITEMS; k++) {
            const float m = fminf(clo[k], chi[k]);
            if (m < bestd[k]) { bestd[k] = m; bestc[k] = ch; }  // strict <: first chunk wins
        }
    }

    // ---- Rescan winning chunk per item: recover first argmin index exactly ----
    float partial = 0.0f;
#pragma unroll
    for (int k = 0; k < ITEMS; k++) {
        const float bd = bestd[k];
        const int jp0 = bestc[k] * CJP;
        int jbest = jp0 * 2;
        bool found = false;
        for (int u = 0; u < CJP; u++) {
            const int jp = jp0 + u;
            const ulonglong2 p01 = sb01[jp];
            const ulonglong2 p23 = sb23[jp];
            const ull        acc = sbb[jp];
            ull t;
            FMA2(t, a0d[k], p01.x, acc);
            FMA2(t, a1d[k], p01.y, t);
            FMA2(t, a2d[k], p23.x, t);
            FMA2(t, a3d[k], p23.y, t);
            float lo, hi;
            unpack2(t, lo, hi);
            if (!found && lo == bd) { jbest = jp * 2;     found = true; }
            if (!found && hi == bd) { jbest = jp * 2 + 1; found = true; }
        }

        const float2 p = sxy[jbest];
        const float dx = ox[k] - p.x;
        const float dy = oy[k] - p.y;
        float xd = sqrtf(dx * dx + dy * dy);
        const float min_d = aa[k] + bd;     // true squared latent distance
        if (min_d > 6.0f) xd = 1.0f;        // LATENT_DIST_THRESHOLD
        partial += xd;
    }

    // ---- Block reduce (deterministic) ----
#pragma unroll
    for (int off = 16; off > 0; off >>= 1)
        partial += __shfl_down_sync(0xffffffffu, partial, off);
    if ((tid & 31) == 0) warp_sums[tid >> 5] = partial;
    __syncthreads();
    if (tid == 0) {
        float s = 0.0f;
#pragma unroll
        for (int w = 0; w < THREADS / 32; w++) s += warp_sums[w];
        g_partials[c] = s;
        __threadfence();
        s_rank = atomicAdd(&g_arrived, 1u);   // last CTA reduces
    }
    __syncthreads();

    if (s_rank == NCTA - 1) {
        __threadfence();                    // acquire partials
        if (tid < 128) {
            float s = 0.0f;
#pragma unroll
            for (int t = 0; t < 8; t++) s += g_partials[tid * 8 + t];
            out[tid] = -s * (1.0f / (1024.0f * 8.0f));
        }
        __syncthreads();
        if (tid == 0) g_arrived = 0;        // reset for next graph replay
    }
}

extern "C" void kernel_launch(void* const* d_in, const int* in_sizes, int n_in,
                              void* d_out, int out_size)
{
    const float* achieved  = (const float*)d_in[0];
    const float* desired   = (const float*)d_in[1];
    const float* norm_mean = (const float*)d_in[2];
    const float* norm_std  = (const float*)d_in[3];
    float* out = (float*)d_out;

    chamfer_pass_kernel<<<NCTA, THREADS>>>(achieved, desired, norm_mean, norm_std, out);
}

// round 8
// speedup vs baseline: 1.2673x; 1.0547x over previous
#include <cuda_runtime.h>
#include <math.h>

// ChamferReward — R8: occupancy push. launch_bounds(256,3) -> 3 CTAs/SM
// (6 warps/SMSP) with a register diet: aa/ox/oy recomputed in the tail from
// gmem (bit-identical FMAs), single fminf chain per item, float2 staging
// loads. Inner loop math identical to R7 (packed fma.rn.f32x2, CJP=8 chunks,
// strict-< chunk fold, bit-identical rescan with exact ==).

#define N_PART  1024
#define NJP     512
#define THREADS 256
#define ITEMS   4
#define CJP     8               // jp per chunk (16 j) — no-spill window
#define NCHUNK  (NJP / CJP)     // 64
#define NCTA    1024

typedef unsigned long long ull;

__device__ float g_partials[NCTA];
__device__ unsigned int g_arrived = 0;

#define FMA2(d, a, b, c) \
    asm("fma.rn.f32x2 %0, %1, %2, %3;" : "=l"(d) : "l"(a), "l"(b), "l"(c))

__device__ __forceinline__ ull pack_dup(float x) {
    ull r;
    unsigned xi = __float_as_uint(x);
    asm("mov.b64 %0, {%1, %1};" : "=l"(r) : "r"(xi));
    return r;
}

__device__ __forceinline__ void unpack2(ull v, float& lo, float& hi) {
    unsigned a, b;
    asm("mov.b64 {%0, %1}, %2;" : "=r"(a), "=r"(b) : "l"(v));
    lo = __uint_as_float(a);
    hi = __uint_as_float(b);
}

__global__ void __launch_bounds__(THREADS, 3)
chamfer_pass_kernel(const float* __restrict__ achieved,
                    const float* __restrict__ desired,
                    const float* __restrict__ norm_mean,
                    const float* __restrict__ norm_std,
                    float* __restrict__ out)
{
    __shared__ ulonglong2 sb01[NJP];   // 8KB: {b0 pair, b1 pair}
    __shared__ ulonglong2 sb23[NJP];   // 8KB: {b2 pair, b3 pair}
    __shared__ ull        sbb[NJP];    // 4KB: |b|^2 pair
    __shared__ float2     sxy[N_PART]; // 8KB
    __shared__ float      warp_sums[THREADS / 32];
    __shared__ unsigned int s_rank;

    const int c    = blockIdx.x;
    const int pass = c & 1;
    const int bv   = c >> 1;

    const float* ownp;
    const float* strp;
    if (pass == 0) { ownp = desired;  strp = achieved; }
    else           { ownp = achieved; strp = desired;  }
    const size_t base = (size_t)bv * (size_t)N_PART * 10;
    ownp += base;
    strp += base;

    const float m0 = __ldg(norm_mean + 0), m1 = __ldg(norm_mean + 1);
    const float m5 = __ldg(norm_mean + 5), m6 = __ldg(norm_mean + 6);
    const float m7 = __ldg(norm_mean + 7), m8 = __ldg(norm_mean + 8);
    const float s0 = __ldg(norm_std  + 0), s1 = __ldg(norm_std  + 1);
    const float s5 = __ldg(norm_std  + 5), s6 = __ldg(norm_std  + 6);
    const float s7 = __ldg(norm_std  + 7), s8 = __ldg(norm_std  + 8);

    const int tid = threadIdx.x;

    // ---- Stage streamed side (normalize, precompute |vis|^2) ----
    // Rows stride 40B; float2 loads at byte offsets 0,16,24,32 are 8B-aligned.
    {
        float* f01 = (float*)sb01;   // per jp: [b0_lo, b0_hi, b1_lo, b1_hi]
        float* f23 = (float*)sb23;   // per jp: [b2_lo, b2_hi, b3_lo, b3_hi]
        float* fbb = (float*)sbb;    // contiguous over j
        for (int i = tid; i < N_PART; i += THREADS) {
            const float2* r2 = (const float2*)(strp + i * 10);
            const float2 q0 = r2[0];   // r0, r1
            const float2 q1 = r2[2];   // r4, r5
            const float2 q2 = r2[3];   // r6, r7
            const float2 q3 = r2[4];   // r8, r9
            float x0 = fmaf(q0.x, s0, m0);
            float x1 = fmaf(q0.y, s1, m1);
            float v0 = fmaf(q1.y, s5, m5);
            float v1 = fmaf(q2.x, s6, m6);
            float v2 = fmaf(q2.y, s7, m7);
            float v3 = fmaf(q3.x, s8, m8);
            const int jp = i >> 1, h = i & 1;
            f01[jp * 4 + h]     = v0;
            f01[jp * 4 + 2 + h] = v1;
            f23[jp * 4 + h]     = v2;
            f23[jp * 4 + 2 + h] = v3;
            fbb[i] = v0 * v0 + v1 * v1 + v2 * v2 + v3 * v3;
            sxy[i] = make_float2(x0, x1);
        }
    }

    // ---- Owned items: a' = -2a, duplicated into both packed halves ----
    // (aa/ox/oy NOT kept live — recomputed bit-identically in the tail.)
    ull a0d[ITEMS], a1d[ITEMS], a2d[ITEMS], a3d[ITEMS];
#pragma unroll
    for (int k = 0; k < ITEMS; k++) {
        const int i = tid + k * THREADS;
        const float2* r2 = (const float2*)(ownp + i * 10);
        const float2 q1 = r2[2];   // r4, r5
        const float2 q2 = r2[3];   // r6, r7
        const float2 q3 = r2[4];   // r8, r9
        float a0 = fmaf(q1.y, s5, m5);
        float a1 = fmaf(q2.x, s6, m6);
        float a2 = fmaf(q2.y, s7, m7);
        float a3 = fmaf(q3.x, s8, m8);
        a0d[k] = pack_dup(-2.0f * a0);
        a1d[k] = pack_dup(-2.0f * a1);
        a2d[k] = pack_dup(-2.0f * a2);
        a3d[k] = pack_dup(-2.0f * a3);
    }

    __syncthreads();

    // ---- Main loop: single-chain value-only chunk minima ----
    float bestd[ITEMS];
    int   bestc[ITEMS];
#pragma unroll
    for (int k = 0; k < ITEMS; k++) { bestd[k] = 3.4e38f; bestc[k] = 0; }

    for (int ch = 0; ch < NCHUNK; ch++) {
        float cm[ITEMS];
#pragma unroll
        for (int k = 0; k < ITEMS; k++) cm[k] = 3.4e38f;

#pragma unroll
        for (int u = 0; u < CJP; u++) {
            const int jp = ch * CJP + u;
            const ulonglong2 p01 = sb01[jp];
            const ulonglong2 p23 = sb23[jp];
            const ull        acc = sbb[jp];
#pragma unroll
            for (int k = 0; k < ITEMS; k++) {
                ull t;
                FMA2(t, a0d[k], p01.x, acc);
                FMA2(t, a1d[k], p01.y, t);
                FMA2(t, a2d[k], p23.x, t);
                FMA2(t, a3d[k], p23.y, t);
                float lo, hi;
                unpack2(t, lo, hi);               // register-naming only
                cm[k] = fminf(cm[k], fminf(lo, hi)); // inner fmin not loop-carried
            }
        }
#pragma unroll
        for (int k = 0; k < ITEMS; k++)
            if (cm[k] < bestd[k]) { bestd[k] = cm[k]; bestc[k] = ch; }  // strict <: first chunk wins
    }

    // ---- Tail: recompute own xy/|a|^2 (bit-identical FMAs), rescan, sum ----
    float partial = 0.0f;
#pragma unroll
    for (int k = 0; k < ITEMS; k++) {
        const int i = tid + k * THREADS;
        const float2* r2 = (const float2*)(ownp + i * 10);
        const float2 q0 = r2[0];
        const float2 q1 = r2[2];
        const float2 q2 = r2[3];
        const float2 q3 = r2[4];
        const float ox = fmaf(q0.x, s0, m0);
        const float oy = fmaf(q0.y, s1, m1);
        const float a0 = fmaf(q1.y, s5, m5);
        const float a1 = fmaf(q2.x, s6, m6);
        const float a2 = fmaf(q2.y, s7, m7);
        const float a3 = fmaf(q3.x, s8, m8);
        const float aa = a0 * a0 + a1 * a1 + a2 * a2 + a3 * a3;

        const float bd = bestd[k];
        const int jp0 = bestc[k] * CJP;
        int jbest = jp0 * 2;
        bool found = false;
        for (int u = 0; u < CJP; u++) {
            const int jp = jp0 + u;
            const ulonglong2 p01 = sb01[jp];
            const ulonglong2 p23 = sb23[jp];
            const ull        acc = sbb[jp];
            ull t;
            FMA2(t, a0d[k], p01.x, acc);
            FMA2(t, a1d[k], p01.y, t);
            FMA2(t, a2d[k], p23.x, t);
            FMA2(t, a3d[k], p23.y, t);
            float lo, hi;
            unpack2(t, lo, hi);
            if (!found && lo == bd) { jbest = jp * 2;     found = true; }
            if (!found && hi == bd) { jbest = jp * 2 + 1; found = true; }
        }

        const float2 p = sxy[jbest];
        const float dx = ox - p.x;
        const float dy = oy - p.y;
        float xd = sqrtf(dx * dx + dy * dy);
        const float min_d = aa + bd;        // true squared latent distance
        if (min_d > 6.0f) xd = 1.0f;        // LATENT_DIST_THRESHOLD
        partial += xd;
    }

    // ---- Block reduce (deterministic) ----
#pragma unroll
    for (int off = 16; off > 0; off >>= 1)
        partial += __shfl_down_sync(0xffffffffu, partial, off);
    if ((tid & 31) == 0) warp_sums[tid >> 5] = partial;
    __syncthreads();
    if (tid == 0) {
        float s = 0.0f;
#pragma unroll
        for (int w = 0; w < THREADS / 32; w++) s += warp_sums[w];
        g_partials[c] = s;
        __threadfence();
        s_rank = atomicAdd(&g_arrived, 1u);   // last CTA reduces
    }
    __syncthreads();

    if (s_rank == NCTA - 1) {
        __threadfence();                    // acquire partials
        if (tid < 128) {
            float s = 0.0f;
#pragma unroll
            for (int t = 0; t < 8; t++) s += g_partials[tid * 8 + t];
            out[tid] = -s * (1.0f / (1024.0f * 8.0f));
        }
        __syncthreads();
        if (tid == 0) g_arrived = 0;        // reset for next graph replay
    }
}

extern "C" void kernel_launch(void* const* d_in, const int* in_sizes, int n_in,
                              void* d_out, int out_size)
{
    const float* achieved  = (const float*)d_in[0];
    const float* desired   = (const float*)d_in[1];
    const float* norm_mean = (const float*)d_in[2];
    const float* norm_std  = (const float*)d_in[3];
    float* out = (float*)d_out;

    chamfer_pass_kernel<<<NCTA, THREADS>>>(achieved, desired, norm_mean, norm_std, out);
}